// round 1
// baseline (speedup 1.0000x reference)
#include <cuda_runtime.h>
#include <math_constants.h>
#include <cstdint>

#define NB 4
#define LL 768
#define HH 8
#define EE 64
#define NH (NB*HH)
#define DD 192        // 3*E augmented feature dim
#define BQ 64
#define BS 64
#define PE_STRIDE 68  // pad for P^T tile

// Scratch: augmented Q'/K' features, layout [nh][d][l] (d-major, l contiguous)
__device__ float g_Qp[(size_t)NH * DD * LL];
__device__ float g_Kp[(size_t)NH * DD * LL];

// ---------------------------------------------------------------------------
// prep: build Q' and K' augmented features.
// thread = (n, h*64+e, l). Coalesced writes along l; scattered reads (cheap).
// ---------------------------------------------------------------------------
__global__ void prep_kernel(const float* __restrict__ q, const float* __restrict__ k,
                            const float* __restrict__ freqs, const float* __restrict__ offsets,
                            const float* __restrict__ gains, const float* __restrict__ gate) {
    int l  = blockIdx.x * 256 + threadIdx.x;   // 0..767
    int he = blockIdx.y;                        // 0..511
    int n  = blockIdx.z;                        // 0..3
    int h  = he >> 6, e = he & 63;

    float fr  = freqs[he];
    float f   = 0.5f / (1.0f + expf(-fr));      // sigmoid(freqs)/2
    float off = offsets[he];
    float gn  = gains[he];
    float g   = (gn > 15.0f) ? gn : log1pf(expf(gn));   // softplus
    float gt  = gate[he];
    float c   = (1.0f - gt) * g * g;

    // phase = 2*pi*f*l (+off); exact-ish range reduction: f*l as two-product
    float lf   = (float)l;
    float fl   = f * lf;
    float resid= fmaf(f, lf, -fl);              // exact low part of f*l
    float frac = (fl - floorf(fl)) + resid;     // fractional turns
    float phk  = 6.28318530717958647692f * frac;
    float cq, sq, ck, sk;
    sincosf(phk + off, &sq, &cq);
    sincosf(phk,       &sk, &ck);

    size_t qi = ((size_t)(n*LL + l)*HH + h)*EE + e;
    float qv = q[qi] * 0.125f;                  // softmax temp folded into Q'
    float kv = k[qi];

    int nh = n*HH + h;
    float* Qb = g_Qp + (size_t)nh * (DD*LL) + l;
    float* Kb = g_Kp + (size_t)nh * (DD*LL) + l;
    Qb[(size_t)(e       )*LL] = qv * gt;
    Qb[(size_t)(e +   EE)*LL] = qv * c * cq;
    Qb[(size_t)(e + 2*EE)*LL] = qv * c * sq;
    Kb[(size_t)(e       )*LL] = kv;
    Kb[(size_t)(e +   EE)*LL] = kv * ck;
    Kb[(size_t)(e + 2*EE)*LL] = kv * sk;
}

// ---------------------------------------------------------------------------
// attn: flash attention, d_qk=192, d_v=64. Block = (l-tile of 64, nh).
// 256 threads = 16x16, 4x4 register tiles. Online softmax, half-warp reduces.
// ---------------------------------------------------------------------------
__global__ __launch_bounds__(256, 1)
void attn_kernel(const float* __restrict__ mask, const float* __restrict__ keylen,
                 const float* __restrict__ values, float* __restrict__ out) {
    extern __shared__ float sm[];
    float* Qs = sm;                 // [DD][64]   d-major
    float* Ks = Qs + DD*64;         // [DD][64]
    float* Vs = Ks + DD*64;         // [64][64]   s-major, e contiguous
    float* Pe = Vs + 64*64;         // [64][PE_STRIDE]  P^T: [s][row]

    const int tid = threadIdx.x;
    const int tx  = tid & 15;       // col group (s or e), 4 each
    const int ty  = tid >> 4;       // row group (l), 4 each
    const int nh  = blockIdx.y;
    const int n   = nh >> 3, h = nh & 7;
    const int l0  = blockIdx.x * BQ;

    // Load Q' tile [192 x 64] (stays resident)
    {
        const float* Qg = g_Qp + (size_t)nh*(DD*LL) + l0;
        for (int d = tid >> 4; d < DD; d += 16)
            *(float4*)&Qs[d*64 + tx*4] = *(const float4*)&Qg[(size_t)d*LL + tx*4];
    }

    float mrow[4], lsum[4], O[4][4];
    #pragma unroll
    for (int i = 0; i < 4; i++) {
        mrow[i] = -CUDART_INF_F; lsum[i] = 0.f;
        #pragma unroll
        for (int j = 0; j < 4; j++) O[i][j] = 0.f;
    }

    for (int it = 0; it < LL/BS; it++) {
        const int s0 = it * BS;
        __syncthreads();   // previous AV done before overwriting Ks/Vs
        {
            const float* Kg = g_Kp + (size_t)nh*(DD*LL) + s0;
            for (int d = tid >> 4; d < DD; d += 16)
                *(float4*)&Ks[d*64 + tx*4] = *(const float4*)&Kg[(size_t)d*LL + tx*4];
            for (int s = tid >> 4; s < BS; s += 16)
                *(float4*)&Vs[s*64 + tx*4] =
                    *(const float4*)&values[((size_t)(n*LL + s0 + s)*HH + h)*EE + tx*4];
        }
        __syncthreads();

        // ---- S = Q' K'^T  (64x64 tile, 192-deep) ----
        float S[4][4];
        #pragma unroll
        for (int i = 0; i < 4; i++)
            #pragma unroll
            for (int j = 0; j < 4; j++) S[i][j] = 0.f;

        #pragma unroll 4
        for (int d = 0; d < DD; d++) {
            float4 qf = *(const float4*)&Qs[d*64 + ty*4];
            float4 kf = *(const float4*)&Ks[d*64 + tx*4];
            float qa[4] = {qf.x, qf.y, qf.z, qf.w};
            float ka[4] = {kf.x, kf.y, kf.z, kf.w};
            #pragma unroll
            for (int i = 0; i < 4; i++)
                #pragma unroll
                for (int j = 0; j < 4; j++)
                    S[i][j] = fmaf(qa[i], ka[j], S[i][j]);
        }

        // additive mask + key-length bias (scaled by temp, since Q' is pre-scaled)
        #pragma unroll
        for (int j = 0; j < 4; j++) {
            int sc = s0 + tx*4 + j;
            float kl = keylen[n*LL + sc];
            #pragma unroll
            for (int i = 0; i < 4; i++) {
                int lrow = l0 + ty*4 + i;
                S[i][j] += 0.125f * (mask[(size_t)lrow*LL + sc] + kl);
            }
        }

        // ---- online softmax; write exp(S - m) transposed into Pe ----
        #pragma unroll
        for (int i = 0; i < 4; i++) {
            float mx = fmaxf(fmaxf(S[i][0], S[i][1]), fmaxf(S[i][2], S[i][3]));
            #pragma unroll
            for (int o = 8; o >= 1; o >>= 1)
                mx = fmaxf(mx, __shfl_xor_sync(0xffffffffu, mx, o, 16));
            float mnew = fmaxf(mrow[i], mx);
            float corr = __expf(mrow[i] - mnew);
            float se = 0.f;
            #pragma unroll
            for (int j = 0; j < 4; j++) {
                float ev = __expf(S[i][j] - mnew);
                Pe[(tx*4 + j)*PE_STRIDE + ty*4 + i] = ev;
                se += ev;
            }
            #pragma unroll
            for (int o = 8; o >= 1; o >>= 1)
                se += __shfl_xor_sync(0xffffffffu, se, o, 16);
            lsum[i] = lsum[i]*corr + se;
            mrow[i] = mnew;
            #pragma unroll
            for (int j = 0; j < 4; j++) O[i][j] *= corr;
        }
        __syncthreads();

        // ---- O += P V  (64-deep) ----
        #pragma unroll 4
        for (int s = 0; s < BS; s++) {
            float4 pf = *(const float4*)&Pe[s*PE_STRIDE + ty*4];
            float4 vf = *(const float4*)&Vs[s*64 + tx*4];
            float pa[4] = {pf.x, pf.y, pf.z, pf.w};
            float va[4] = {vf.x, vf.y, vf.z, vf.w};
            #pragma unroll
            for (int i = 0; i < 4; i++)
                #pragma unroll
                for (int j = 0; j < 4; j++)
                    O[i][j] = fmaf(pa[i], va[j], O[i][j]);
        }
    }

    // epilogue: normalize and store
    #pragma unroll
    for (int i = 0; i < 4; i++) {
        float inv = 1.0f / lsum[i];
        float4 ov = make_float4(O[i][0]*inv, O[i][1]*inv, O[i][2]*inv, O[i][3]*inv);
        *(float4*)&out[((size_t)(n*LL + l0 + ty*4 + i)*HH + h)*EE + tx*4] = ov;
    }
}

// ---------------------------------------------------------------------------
extern "C" void kernel_launch(void* const* d_in, const int* in_sizes, int n_in,
                              void* d_out, int out_size) {
    const float* queries = (const float*)d_in[0];
    const float* keys    = (const float*)d_in[1];
    const float* values  = (const float*)d_in[2];
    const float* mask    = (const float*)d_in[3];
    const float* keylen  = (const float*)d_in[4];
    const float* freqs   = (const float*)d_in[5];
    const float* offsets = (const float*)d_in[6];
    const float* gains   = (const float*)d_in[7];
    const float* gate    = (const float*)d_in[8];
    float* out = (float*)d_out;

    prep_kernel<<<dim3(LL/256, HH*EE, NB), 256>>>(queries, keys, freqs, offsets, gains, gate);

    const size_t smem = (size_t)(DD*64 + DD*64 + 64*64 + 64*PE_STRIDE) * sizeof(float);
    cudaFuncSetAttribute(attn_kernel, cudaFuncAttributeMaxDynamicSharedMemorySize, (int)smem);
    attn_kernel<<<dim3(LL/BQ, NH), 256, smem>>>(mask, keylen, values, out);
}

// round 3
// speedup vs baseline: 3.3695x; 3.3695x over previous
#include <cuda_runtime.h>
#include <cuda_bf16.h>
#include <math_constants.h>
#include <cstdint>

#define LL 768
#define HH 8
#define EE 64
#define NH 32
#define DD 192
#define BQ 64
#define NTILE 12
#define KSTR 200   // padded smem row stride (bf16) for K' tiles -> conflict-free B loads
#define VSTR 72    // padded smem row stride (bf16) for V^T tiles

// ---------------- scratch (device globals; no allocs) ----------------
__device__ __nv_bfloat16 g_Qhi[(size_t)NH * LL * DD];
__device__ __nv_bfloat16 g_Qlo[(size_t)NH * LL * DD];
__device__ __nv_bfloat16 g_Khi[(size_t)NH * LL * DD];
__device__ __nv_bfloat16 g_Klo[(size_t)NH * LL * DD];
__device__ __nv_bfloat16 g_Vhi[(size_t)NH * EE * LL];   // transposed [nh][e][s]
__device__ __nv_bfloat16 g_Vlo[(size_t)NH * EE * LL];

// m16n8k16 row.col bf16 MMA, f32 accumulate (portable HMMA path)
__device__ __forceinline__ void mma_bf16(float* c, const uint32_t* a, uint32_t b0, uint32_t b1) {
    asm volatile("mma.sync.aligned.m16n8k16.row.col.f32.bf16.bf16.f32 "
                 "{%0,%1,%2,%3}, {%4,%5,%6,%7}, {%8,%9}, {%0,%1,%2,%3};"
                 : "+f"(c[0]), "+f"(c[1]), "+f"(c[2]), "+f"(c[3])
                 : "r"(a[0]), "r"(a[1]), "r"(a[2]), "r"(a[3]), "r"(b0), "r"(b1));
}

__device__ __forceinline__ uint32_t pack_hi(float x, float y, uint32_t& lo) {
    __nv_bfloat162 h2;
    h2.x = __float2bfloat16(x);
    h2.y = __float2bfloat16(y);
    __nv_bfloat162 l2;
    l2.x = __float2bfloat16(x - __bfloat162float(h2.x));
    l2.y = __float2bfloat16(y - __bfloat162float(h2.y));
    lo = *(uint32_t*)&l2;
    return *(uint32_t*)&h2;
}

// ---------------------------------------------------------------------------
// prep_qk: augmented Q'/K' (d=192) as bf16 hi/lo, row-major [nh][l][192].
// ---------------------------------------------------------------------------
__global__ void prep_qk(const float* __restrict__ q, const float* __restrict__ k,
                        const float* __restrict__ freqs, const float* __restrict__ offsets,
                        const float* __restrict__ gains, const float* __restrict__ gate) {
    int e  = threadIdx.x & 63;
    int l  = blockIdx.x * 4 + (threadIdx.x >> 6);
    int nh = blockIdx.y;
    int n = nh >> 3, h = nh & 7;
    int he = h * 64 + e;

    float fr  = freqs[he];
    float f   = 0.5f / (1.0f + expf(-fr));
    float off = offsets[he];
    float gn  = gains[he];
    float g   = (gn > 15.0f) ? gn : log1pf(expf(gn));
    float gt  = gate[he];
    float c   = (1.0f - gt) * g * g;

    float lf    = (float)l;
    float fl    = f * lf;
    float resid = fmaf(f, lf, -fl);
    float frac  = (fl - floorf(fl)) + resid;
    float phk   = 6.28318530717958647692f * frac;
    float cq, sq, ck, sk;
    sincosf(phk + off, &sq, &cq);
    sincosf(phk,       &sk, &ck);

    size_t qi = ((size_t)(n * LL + l) * HH + h) * EE + e;
    float qv = q[qi] * 0.125f;            // softmax temp folded into Q'
    float kv = k[qi];

    float qs[3] = { qv * gt, qv * c * cq, qv * c * sq };
    float ks[3] = { kv,      kv * ck,     kv * sk     };

    size_t base = ((size_t)nh * LL + l) * DD;
    #pragma unroll
    for (int kk = 0; kk < 3; kk++) {
        float v = qs[kk];
        __nv_bfloat16 hi = __float2bfloat16(v);
        g_Qhi[base + kk * 64 + e] = hi;
        g_Qlo[base + kk * 64 + e] = __float2bfloat16(v - __bfloat162float(hi));
        float w = ks[kk];
        __nv_bfloat16 whi = __float2bfloat16(w);
        g_Khi[base + kk * 64 + e] = whi;
        g_Klo[base + kk * 64 + e] = __float2bfloat16(w - __bfloat162float(whi));
    }
}

// ---------------------------------------------------------------------------
// prep_v: V transposed to [nh][e][s] bf16 hi/lo (s contiguous).
// ---------------------------------------------------------------------------
__global__ void prep_v(const float* __restrict__ values) {
    __shared__ float sm[64 * 65];
    int t = blockIdx.x, nh = blockIdx.y;
    int n = nh >> 3, h = nh & 7;
    int s0 = t * 64;

    #pragma unroll
    for (int i = 0; i < 16; i++) {
        int idx = threadIdx.x + i * 256;
        int r = idx >> 6, e = idx & 63;
        sm[e * 65 + r] = values[((size_t)(n * LL + s0 + r) * HH + h) * EE + e];
    }
    __syncthreads();

    #pragma unroll
    for (int i = 0; i < 8; i++) {
        int pid = threadIdx.x + i * 256;
        int e = pid >> 5, s2 = pid & 31;
        float v0 = sm[e * 65 + 2 * s2];
        float v1 = sm[e * 65 + 2 * s2 + 1];
        __nv_bfloat162 hi2, lo2;
        hi2.x = __float2bfloat16(v0);
        hi2.y = __float2bfloat16(v1);
        lo2.x = __float2bfloat16(v0 - __bfloat162float(hi2.x));
        lo2.y = __float2bfloat16(v1 - __bfloat162float(hi2.y));
        size_t o = ((size_t)nh * EE + e) * LL + s0 + 2 * s2;
        *(uint32_t*)(g_Vhi + o) = *(uint32_t*)&hi2;
        *(uint32_t*)(g_Vlo + o) = *(uint32_t*)&lo2;
    }
}

// ---------------------------------------------------------------------------
// attn: flash attention on HMMA (mma.sync bf16, 3-product hi/lo split).
// Block = 4 warps = 64 q-rows (warp owns 16). 12 s-tiles of 64.
// ---------------------------------------------------------------------------
__global__ __launch_bounds__(128)
void attn_kernel(const float* __restrict__ mask, const float* __restrict__ keylen,
                 float* __restrict__ out) {
    extern __shared__ __nv_bfloat16 smem[];
    __nv_bfloat16* sKhi = smem;                      // [64][KSTR]
    __nv_bfloat16* sKlo = smem + 64 * KSTR;
    __nv_bfloat16* sVhi = smem + 2 * 64 * KSTR;      // [64][VSTR]
    __nv_bfloat16* sVlo = smem + 2 * 64 * KSTR + 64 * VSTR;

    const int tid  = threadIdx.x;
    const int w    = tid >> 5;
    const int lane = tid & 31;
    const int g    = lane >> 2, t = lane & 3;
    const int nh   = blockIdx.y;
    const int nb   = nh >> 3, h = nh & 7;
    const int l0   = blockIdx.x * BQ;
    const int row0 = l0 + w * 16 + g;

    // ---- Q fragments, register resident (reused for all 12 s-tiles) ----
    uint32_t aQh[12][4], aQl[12][4];
    {
        const __nv_bfloat16* qh = g_Qhi + ((size_t)nh * LL + row0) * DD;
        const __nv_bfloat16* ql = g_Qlo + ((size_t)nh * LL + row0) * DD;
        #pragma unroll
        for (int c = 0; c < 12; c++) {
            int d0 = c * 16 + 2 * t;
            aQh[c][0] = *(const uint32_t*)(qh + d0);
            aQh[c][1] = *(const uint32_t*)(qh + 8 * DD + d0);
            aQh[c][2] = *(const uint32_t*)(qh + d0 + 8);
            aQh[c][3] = *(const uint32_t*)(qh + 8 * DD + d0 + 8);
            aQl[c][0] = *(const uint32_t*)(ql + d0);
            aQl[c][1] = *(const uint32_t*)(ql + 8 * DD + d0);
            aQl[c][2] = *(const uint32_t*)(ql + d0 + 8);
            aQl[c][3] = *(const uint32_t*)(ql + 8 * DD + d0 + 8);
        }
    }

    float O[8][4];
    #pragma unroll
    for (int n = 0; n < 8; n++)
        #pragma unroll
        for (int j = 0; j < 4; j++) O[n][j] = 0.f;
    float m0 = -CUDART_INF_F, m1 = -CUDART_INF_F, ls0 = 0.f, ls1 = 0.f;

    const float* mrow0b = mask + (size_t)row0 * LL;
    const float* mrow1b = mrow0b + 8 * LL;
    const float* klb    = keylen + (size_t)nb * LL;

    for (int it = 0; it < NTILE; it++) {
        __syncthreads();
        // ---- cooperative tile fill (row-major -> padded smem) ----
        {
            const uint4* sH = (const uint4*)(g_Khi + ((size_t)nh * LL + it * 64) * DD);
            const uint4* sL = (const uint4*)(g_Klo + ((size_t)nh * LL + it * 64) * DD);
            #pragma unroll
            for (int i = 0; i < 12; i++) {
                int idx = tid + i * 128;
                int r = idx / 24, c = idx % 24;
                *(uint4*)(sKhi + r * KSTR + c * 8) = sH[idx];
                *(uint4*)(sKlo + r * KSTR + c * 8) = sL[idx];
            }
            #pragma unroll
            for (int i = 0; i < 4; i++) {
                int idx = tid + i * 128;
                int r = idx / 8, c = idx % 8;
                size_t go = ((size_t)nh * EE + r) * LL + it * 64 + c * 8;
                *(uint4*)(sVhi + r * VSTR + c * 8) = *(const uint4*)(g_Vhi + go);
                *(uint4*)(sVlo + r * VSTR + c * 8) = *(const uint4*)(g_Vlo + go);
            }
        }
        __syncthreads();

        // ---- S = Q' K'^T : 8 n-tiles x 12 k-chunks x 3 products ----
        float S[8][4];
        #pragma unroll
        for (int n = 0; n < 8; n++)
            #pragma unroll
            for (int j = 0; j < 4; j++) S[n][j] = 0.f;

        #pragma unroll
        for (int n = 0; n < 8; n++) {
            const __nv_bfloat16* kh = sKhi + (n * 8 + g) * KSTR + 2 * t;
            const __nv_bfloat16* kl = sKlo + (n * 8 + g) * KSTR + 2 * t;
            #pragma unroll
            for (int c = 0; c < 12; c++) {
                uint32_t bh0 = *(const uint32_t*)(kh + c * 16);
                uint32_t bh1 = *(const uint32_t*)(kh + c * 16 + 8);
                uint32_t bl0 = *(const uint32_t*)(kl + c * 16);
                uint32_t bl1 = *(const uint32_t*)(kl + c * 16 + 8);
                mma_bf16(S[n], aQh[c], bh0, bh1);
                mma_bf16(S[n], aQh[c], bl0, bl1);
                mma_bf16(S[n], aQl[c], bh0, bh1);
            }
        }

        // ---- bias: 0.125 * (mask + keylen) ----
        {
            const float* mr0 = mrow0b + it * 64;
            const float* mr1 = mrow1b + it * 64;
            const float* kl  = klb + it * 64;
            #pragma unroll
            for (int n = 0; n < 8; n++) {
                int sc = n * 8 + 2 * t;
                float2 a0 = *(const float2*)(mr0 + sc);
                float2 a1 = *(const float2*)(mr1 + sc);
                float2 kk = *(const float2*)(kl + sc);
                S[n][0] += 0.125f * (a0.x + kk.x);
                S[n][1] += 0.125f * (a0.y + kk.y);
                S[n][2] += 0.125f * (a1.x + kk.x);
                S[n][3] += 0.125f * (a1.y + kk.y);
            }
        }

        // ---- online softmax (rows quad-local) ----
        float mx0 = S[0][0], mx1 = S[0][2];
        #pragma unroll
        for (int n = 0; n < 8; n++) {
            mx0 = fmaxf(mx0, fmaxf(S[n][0], S[n][1]));
            mx1 = fmaxf(mx1, fmaxf(S[n][2], S[n][3]));
        }
        mx0 = fmaxf(mx0, __shfl_xor_sync(0xffffffffu, mx0, 1));
        mx0 = fmaxf(mx0, __shfl_xor_sync(0xffffffffu, mx0, 2));
        mx1 = fmaxf(mx1, __shfl_xor_sync(0xffffffffu, mx1, 1));
        mx1 = fmaxf(mx1, __shfl_xor_sync(0xffffffffu, mx1, 2));
        float m0n = fmaxf(m0, mx0), m1n = fmaxf(m1, mx1);
        float c0 = __expf(m0 - m0n), c1 = __expf(m1 - m1n);
        m0 = m0n; m1 = m1n;
        float s0 = 0.f, s1 = 0.f;
        #pragma unroll
        for (int n = 0; n < 8; n++) {
            S[n][0] = __expf(S[n][0] - m0n);
            S[n][1] = __expf(S[n][1] - m0n);
            S[n][2] = __expf(S[n][2] - m1n);
            S[n][3] = __expf(S[n][3] - m1n);
            s0 += S[n][0] + S[n][1];
            s1 += S[n][2] + S[n][3];
            O[n][0] *= c0; O[n][1] *= c0;
            O[n][2] *= c1; O[n][3] *= c1;
        }
        s0 += __shfl_xor_sync(0xffffffffu, s0, 1);
        s0 += __shfl_xor_sync(0xffffffffu, s0, 2);
        s1 += __shfl_xor_sync(0xffffffffu, s1, 1);
        s1 += __shfl_xor_sync(0xffffffffu, s1, 2);
        ls0 = ls0 * c0 + s0;
        ls1 = ls1 * c1 + s1;

        // ---- P -> bf16 hi/lo A-fragments (in-register, no smem) ----
        uint32_t ph[4][4], pl[4][4];
        #pragma unroll
        for (int kc = 0; kc < 4; kc++) {
            ph[kc][0] = pack_hi(S[2*kc][0],   S[2*kc][1],   pl[kc][0]);
            ph[kc][1] = pack_hi(S[2*kc][2],   S[2*kc][3],   pl[kc][1]);
            ph[kc][2] = pack_hi(S[2*kc+1][0], S[2*kc+1][1], pl[kc][2]);
            ph[kc][3] = pack_hi(S[2*kc+1][2], S[2*kc+1][3], pl[kc][3]);
        }

        // ---- O += P V : 8 e-tiles x 4 s-chunks x 3 products ----
        #pragma unroll
        for (int n = 0; n < 8; n++) {
            const __nv_bfloat16* vh = sVhi + (n * 8 + g) * VSTR + 2 * t;
            const __nv_bfloat16* vl = sVlo + (n * 8 + g) * VSTR + 2 * t;
            #pragma unroll
            for (int kc = 0; kc < 4; kc++) {
                uint32_t bh0 = *(const uint32_t*)(vh + kc * 16);
                uint32_t bh1 = *(const uint32_t*)(vh + kc * 16 + 8);
                uint32_t bl0 = *(const uint32_t*)(vl + kc * 16);
                uint32_t bl1 = *(const uint32_t*)(vl + kc * 16 + 8);
                mma_bf16(O[n], ph[kc], bh0, bh1);
                mma_bf16(O[n], ph[kc], bl0, bl1);
                mma_bf16(O[n], pl[kc], bh0, bh1);
            }
        }
    }

    // ---- epilogue ----
    float inv0 = 1.0f / ls0, inv1 = 1.0f / ls1;
    float* o0 = out + ((size_t)(nb * LL + row0) * HH + h) * EE;
    float* o1 = o0 + 8 * HH * EE;
    #pragma unroll
    for (int n = 0; n < 8; n++) {
        int e = n * 8 + 2 * t;
        *(float2*)(o0 + e) = make_float2(O[n][0] * inv0, O[n][1] * inv0);
        *(float2*)(o1 + e) = make_float2(O[n][2] * inv1, O[n][3] * inv1);
    }
}

// ---------------------------------------------------------------------------
extern "C" void kernel_launch(void* const* d_in, const int* in_sizes, int n_in,
                              void* d_out, int out_size) {
    const float* queries = (const float*)d_in[0];
    const float* keys    = (const float*)d_in[1];
    const float* values  = (const float*)d_in[2];
    const float* mask    = (const float*)d_in[3];
    const float* keylen  = (const float*)d_in[4];
    const float* freqs   = (const float*)d_in[5];
    const float* offsets = (const float*)d_in[6];
    const float* gains   = (const float*)d_in[7];
    const float* gate    = (const float*)d_in[8];
    float* out = (float*)d_out;

    prep_qk<<<dim3(LL / 4, NH), 256>>>(queries, keys, freqs, offsets, gains, gate);
    prep_v<<<dim3(NTILE, NH), 256>>>(values);

    const int smem = (2 * 64 * KSTR + 2 * 64 * VSTR) * 2;  // 69632 B
    cudaFuncSetAttribute(attn_kernel, cudaFuncAttributeMaxDynamicSharedMemorySize, smem);
    attn_kernel<<<dim3(LL / BQ, NH), 128, smem>>>(mask, keylen, out);
}